// round 12
// baseline (speedup 1.0000x reference)
#include <cuda_runtime.h>
#include <math.h>

#define BB 16
#define TT 1024
#define DD 256
#define KK 64
#define NBLK2 (BB * KK * 2)
#define LOG2PI 1.8378770664093453f
#define HALF_L2PI 0.91893853320467274f
#define LN2 0.69314718055994531f

// ---- persistent device scratch (zero-initialized at module load; the
//      finalizer restores zeros so every launch sees the same state) ----
__device__ double g_acc;
__device__ int    g_done;

// Stirling correction poly: 1/(12z) - 1/(360z^3) + 1/(1260z^5)
__device__ __forceinline__ float stir(float r) {
    float r2 = r * r;
    return r * fmaf(-r2, fmaf(-r2, 7.9365079e-4f, 2.7777778e-3f), 8.3333333e-2f);
}

// direct Stirling lgamma — valid for x >= ~2.5 (abs err < ~1e-6)
__device__ __forceinline__ float lgf_s(float x) {
    float lx = __logf(x);
    float r  = __fdividef(1.0f, x);
    return fmaf(x - 0.5f, lx, -x) + HALF_L2PI + stir(r);
}

// g(x) = lgamma(x) + 0.5*log(x) = x*ln x - x + C + stir  — for x >= ~2.5
__device__ __forceinline__ float g_fn(float x) {
    float lx = __logf(x);
    float r  = __fdividef(1.0f, x);
    return fmaf(x, lx, -x) + HALF_L2PI + stir(r);
}

// shift-by-2 lgamma — valid for x >= ~0.5
__device__ __forceinline__ float lgf2(float x) {
    float z  = x + 2.0f;
    float lx = __logf(z);
    float r  = __fdividef(1.0f, z);
    float lg = fmaf(z - 0.5f, lx, -z) + HALF_L2PI + stir(r);
    return lg - __logf(x * (x + 1.0f));
}

#define PROC4(xv)                                              \
    do {                                                        \
        float u0 = __log2f((xv).x > 0.0f ? (xv).x : 1.0f);      \
        float u1 = __log2f((xv).y > 0.0f ? (xv).y : 1.0f);      \
        float u2 = __log2f((xv).z > 0.0f ? (xv).z : 1.0f);      \
        float u3 = __log2f((xv).w > 0.0f ? (xv).w : 1.0f);      \
        s10 += u0; s11 += u1; s12 += u2; s13 += u3;             \
        s20 = fmaf(u0, u0, s20); s21 = fmaf(u1, u1, s21);       \
        s22 = fmaf(u2, u2, s22); s23 = fmaf(u3, u3, s23);       \
        n10 += ((xv).x > 0.0f); n11 += ((xv).y > 0.0f);         \
        n12 += ((xv).z > 0.0f); n13 += ((xv).w > 0.0f);         \
    } while (0)

// ---- single fused kernel: block = (b, k, dim-half); 128 threads ----
// phase 1: thread = (row-group g = tid>>5, column-quad c = tid&31), float4 loads
// phase 2: reduce groups via smem; thread = local dim; verified epilogue
__global__ void __launch_bounds__(128) k_main(const float* __restrict__ X,
                                              const int* __restrict__ z,
                                              const float* __restrict__ loc,
                                              const float* __restrict__ lcg,
                                              const float* __restrict__ lsc,
                                              const float* __restrict__ spl,
                                              float* __restrict__ out) {
    int bk   = blockIdx.x;
    int b    = bk >> 7;                               // / (KK*2)
    int k    = (bk >> 1) & (KK - 1);
    int half = bk & 1;
    int tid  = threadIdx.x;

    // ---- unordered bucket build (suffstats are order-independent) ----
    __shared__ int tbuf[TT];                          // stores t*DD
    __shared__ int cnt_s;
    if (tid == 0) cnt_s = 0;
    __syncthreads();
    const int4* zp = reinterpret_cast<const int4*>(z + b * TT);
    int4 zq0 = zp[tid];                               // t = 4*tid ..
    int4 zq1 = zp[tid + 128];                         // t = 512 + 4*tid ..
    int t0 = tid * 4;
    if (zq0.x == k) tbuf[atomicAdd(&cnt_s, 1)] = (t0 + 0) * DD;
    if (zq0.y == k) tbuf[atomicAdd(&cnt_s, 1)] = (t0 + 1) * DD;
    if (zq0.z == k) tbuf[atomicAdd(&cnt_s, 1)] = (t0 + 2) * DD;
    if (zq0.w == k) tbuf[atomicAdd(&cnt_s, 1)] = (t0 + 3) * DD;
    if (zq1.x == k) tbuf[atomicAdd(&cnt_s, 1)] = (512 + t0 + 0) * DD;
    if (zq1.y == k) tbuf[atomicAdd(&cnt_s, 1)] = (512 + t0 + 1) * DD;
    if (zq1.z == k) tbuf[atomicAdd(&cnt_s, 1)] = (512 + t0 + 2) * DD;
    if (zq1.w == k) tbuf[atomicAdd(&cnt_s, 1)] = (512 + t0 + 3) * DD;
    __syncthreads();
    int cnt = cnt_s;

    // ---- phase 1: float4 gather + per-thread partial suffstats ----
    int g  = tid >> 5;                                // row group 0..3
    int c  = tid & 31;                                // column quad within half
    const float* Xb = X + (size_t)b * TT * DD + half * 128 + c * 4;

    float n10 = 0, n11 = 0, n12 = 0, n13 = 0;
    float s10 = 0, s11 = 0, s12 = 0, s13 = 0;
    float s20 = 0, s21 = 0, s22 = 0, s23 = 0;

    int i = g;
    for (; i + 4 < cnt; i += 8) {                     // 2 rows in flight
        float4 xa = *reinterpret_cast<const float4*>(Xb + tbuf[i]);
        float4 xb = *reinterpret_cast<const float4*>(Xb + tbuf[i + 4]);
        PROC4(xa); PROC4(xb);
    }
    if (i < cnt) {
        float4 xa = *reinterpret_cast<const float4*>(Xb + tbuf[i]);
        PROC4(xa);
    }

    // ---- cross-group reduction via padded smem stage (deterministic) ----
    __shared__ float stg[4 * 32 * 13];                // pad 12->13: conflict-free
    float* my = stg + (g * 32 + c) * 13;
    my[0] = n10; my[1] = n11; my[2]  = n12; my[3]  = n13;
    my[4] = s10; my[5] = s11; my[6]  = s12; my[7]  = s13;
    my[8] = s20; my[9] = s21; my[10] = s22; my[11] = s23;
    __syncthreads();

    int dc = tid >> 2, dj = tid & 3;                  // local dim = 4*dc + dj = tid
    float n1 = 0.0f, S1 = 0.0f, S2 = 0.0f;
#pragma unroll
    for (int gg = 0; gg < 4; ++gg) {
        const float* p = stg + (gg * 32 + dc) * 13;
        n1 += p[dj]; S1 += p[4 + dj]; S2 += p[8 + dj];
    }
    S1 *= LN2; S2 *= LN2 * LN2;                       // log2 -> natural log

    // ---- epilogue from sufficient statistics (verified math) ----
    int d = half * 128 + tid;                         // global dim
    float cc   = __expf(lcg[d]);
    float m0   = loc[d];
    float lb0  = lsc[d];
    float b0   = __expf(lb0);
    float kap0 = 2.0f * cc + 3.0f;
    float tc4  = kap0 + 1.0f;
    float c00  = tc4 * __expf(spl[d]);
    float cntf = (float)cnt;
    float n0f  = cntf - n1;

    float rn   = (n1 > 0.0f) ? __fdividef(1.0f, n1) : 0.0f;
    float tbar = S1 * rn;
    float dm   = tbar - m0;
    float bb   = b0 + 0.5f * (S2 - S1 * tbar)
               + __fdividef(kap0 * n1 * dm * dm, 2.0f * (kap0 + n1));

    float acc = -S1;                                  // Jacobian
    acc -= 0.5f * n1 * lb0 + fmaf(0.5f, n1, cc) * (__logf(bb) - lb0);
    acc += lgf2(fmaf(0.5f, n1, cc)) - lgf2(cc)
         + g_fn(kap0 + n1) - g_fn(kap0)
         - 0.5f * n1 * LOG2PI;
    acc += lgf_s(c00 + n0f) - lgf_s(c00)
         + lgf_s(tc4 + c00) - lgf_s(tc4 + c00 + cntf);

    // CRP numerator for this (b,k): lgamma(cnt)  (ALPHA=1) — half 0 only
    if (tid == 0 && half == 0 && cnt > 0) acc += lgf2(cntf);

    // ---- block reduce (128 threads) ----
#pragma unroll
    for (int o = 16; o; o >>= 1) acc += __shfl_xor_sync(0xffffffffu, acc, o);
    __shared__ float wsum[4];
    int lane = tid & 31, wid = tid >> 5;
    if (lane == 0) wsum[wid] = acc;
    __syncthreads();
    if (tid == 0) {
        float s = wsum[0] + wsum[1] + wsum[2] + wsum[3];
        atomicAdd(&g_acc, (double)s);
        __threadfence();
        int prev = atomicAdd(&g_done, 1);
        if (prev == NBLK2 - 1) {
            double tot = atomicAdd(&g_acc, 0.0);      // read-after-fence
            tot -= (double)BB * (double)lgf_s((float)(TT + 1));  // CRP denominator
            out[0] = (float)(-tot / (double)BB);
            g_acc  = 0.0;                             // restore for next replay
            g_done = 0;
        }
    }
}

extern "C" void kernel_launch(void* const* d_in, const int* in_sizes, int n_in,
                              void* d_out, int out_size) {
    const float* X   = (const float*)d_in[0];
    const int*   z   = (const int*)d_in[1];
    const float* loc = (const float*)d_in[2];
    const float* lcg = (const float*)d_in[3];
    const float* lsc = (const float*)d_in[4];
    const float* spl = (const float*)d_in[5];

    k_main<<<NBLK2, 128>>>(X, z, loc, lcg, lsc, spl, (float*)d_out);
}